// round 8
// baseline (speedup 1.0000x reference)
#include <cuda_runtime.h>
#include <cstdint>

#define Bn 32
#define Tn 1024
#define In 512
#define Hn 1024
#define Gn 4096   // 4*Hn
#define NB 128    // persistent blocks (<=148 SMs, 1 block/SM)

// ---------------- device scratch (static: no allocation allowed) ----------------
__device__ float g_xpre[(size_t)Tn * Bn * Gn];  // [T][B][4H], biases folded in
__device__ float g_h[2 * Bn * Hn];              // ping-pong hidden state
__device__ float g_c[Bn * Hn];                  // cell state (block-exclusive ranges)
__device__ unsigned g_count;                    // grid barrier arrivals (monotonic)
__device__ volatile unsigned g_gen;             // grid barrier generation

typedef unsigned long long ull;

__device__ __forceinline__ ull fma2(ull a, ull b, ull c) {
    ull d; asm("fma.rn.f32x2 %0, %1, %2, %3;" : "=l"(d) : "l"(a), "l"(b), "l"(c)); return d;
}
__device__ __forceinline__ ull pack2(float lo, float hi) {
    ull r; asm("mov.b64 %0, {%1, %2};" : "=l"(r) : "f"(lo), "f"(hi)); return r;
}
__device__ __forceinline__ void unpack2(ull v, float& a, float& b) {
    asm("mov.b64 {%0, %1}, %2;" : "=f"(a), "=f"(b) : "l"(v));
}

// ---------------- phase 1 (+init): Xpre = inputs @ W_ih^T + b_ih + b_hh ----------------
// M = T*B = 32768 (row m = t*32+b), N = 4096, K = 512.
// 128x128 tiles, BK=16, 256 threads, 8x8 micro tile, f32x2.
// Staging: sr = tid&127 (row), sk = (tid>>7)*8 -> warp lanes hit 32 distinct banks.
// Inner B reads: 2x LDS.128 (conflict-free broadcast).
__global__ __launch_bounds__(256) void prep_gemm(
    const float* __restrict__ X,    // [B][T][I]
    const float* __restrict__ Wih,  // [4H][I]
    const float* __restrict__ bih,
    const float* __restrict__ bhh)
{
    __shared__ float As[2][16][132];
    __shared__ float Bs[2][16][132];

    int tid = threadIdx.x;
    int bx = blockIdx.x, by = blockIdx.y;

    // ---- fused init of state/barrier (first 256 blocks cover it) ----
    {
        int fb = by * 32 + bx;
        int idx = fb * 256 + tid;
        if (idx < 2 * Bn * Hn) g_h[idx] = 0.0f;
        if (idx < Bn * Hn)     g_c[idx] = 0.0f;
        if (idx == 0) { g_count = 0; g_gen = 0; }
    }

    int sr = tid & 127;          // tile row / B row
    int sk = (tid >> 7) * 8;     // 0 or 8
    int mg = by * 128 + sr;      // global output row (m = t*32 + b)
    const float* arow = X + ((size_t)(mg & 31) * Tn + (mg >> 5)) * In;
    const float* brow = Wih + (size_t)(bx * 128 + sr) * In;

    int tm = tid >> 4;           // 0..15 -> rows tm*8..tm*8+7
    int tn = tid & 15;           // 0..15 -> cols tn*8..tn*8+7

    ull acc[8][4];
#pragma unroll
    for (int i = 0; i < 8; i++)
#pragma unroll
        for (int p = 0; p < 4; p++) acc[i][p] = 0ULL;

    float4 pa0, pa1, pb0, pb1;
    pa0 = *(const float4*)(arow + sk);
    pa1 = *(const float4*)(arow + sk + 4);
    pb0 = *(const float4*)(brow + sk);
    pb1 = *(const float4*)(brow + sk + 4);
#pragma unroll
    for (int j = 0; j < 4; j++) {
        As[0][sk + j][sr]     = ((const float*)&pa0)[j];
        As[0][sk + 4 + j][sr] = ((const float*)&pa1)[j];
        Bs[0][sk + j][sr]     = ((const float*)&pb0)[j];
        Bs[0][sk + 4 + j][sr] = ((const float*)&pb1)[j];
    }
    __syncthreads();

    for (int kt = 0; kt < 32; kt++) {
        if (kt < 31) {
            int k0 = (kt + 1) * 16;
            pa0 = *(const float4*)(arow + k0 + sk);
            pa1 = *(const float4*)(arow + k0 + sk + 4);
            pb0 = *(const float4*)(brow + k0 + sk);
            pb1 = *(const float4*)(brow + k0 + sk + 4);
        }
        int buf = kt & 1;
#pragma unroll
        for (int k = 0; k < 16; k++) {
            float a[8];
            *(float4*)&a[0] = *(const float4*)&As[buf][k][tm * 8];
            *(float4*)&a[4] = *(const float4*)&As[buf][k][tm * 8 + 4];
            float4 b0 = *(const float4*)&Bs[buf][k][tn * 8];
            float4 b1 = *(const float4*)&Bs[buf][k][tn * 8 + 4];
            ull bv[4];
            bv[0] = *(const ull*)&b0.x; bv[1] = *(const ull*)&b0.z;
            bv[2] = *(const ull*)&b1.x; bv[3] = *(const ull*)&b1.z;
#pragma unroll
            for (int i = 0; i < 8; i++) {
                ull ap = pack2(a[i], a[i]);
#pragma unroll
                for (int p = 0; p < 4; p++)
                    acc[i][p] = fma2(ap, bv[p], acc[i][p]);
            }
        }
        if (kt < 31) {
            int nb = (kt + 1) & 1;
#pragma unroll
            for (int j = 0; j < 4; j++) {
                As[nb][sk + j][sr]     = ((const float*)&pa0)[j];
                As[nb][sk + 4 + j][sr] = ((const float*)&pa1)[j];
                Bs[nb][sk + j][sr]     = ((const float*)&pb0)[j];
                Bs[nb][sk + 4 + j][sr] = ((const float*)&pb1)[j];
            }
        }
        __syncthreads();
    }

    int ng = bx * 128 + tn * 8;
    float bias[8];
#pragma unroll
    for (int j = 0; j < 8; j++) bias[j] = bih[ng + j] + bhh[ng + j];
#pragma unroll
    for (int i = 0; i < 8; i++) {
        int m = by * 128 + tm * 8 + i;
        float* dst = g_xpre + (size_t)m * Gn + ng;
#pragma unroll
        for (int p = 0; p < 4; p++) {
            float lo, hi; unpack2(acc[i][p], lo, hi);
            *(float2*)(dst + 2 * p) = make_float2(lo + bias[2 * p], hi + bias[2 * p + 1]);
        }
    }
}

// ---------------- phase 2: persistent LSTM over all T steps ----------------
#define WS_STRIDE 36
#define WS_FLOATS (Hn * WS_STRIDE)            // 36864
#define HD_ROW 66
#define HD_HALF (64 * HD_ROW)                 // one kk window, one buf
#define HD_FLOATS (2 * 2 * HD_HALF)           // 16896
#define GB_FLOATS (32 * 33)                   // 1056
#define SMEM2_FLOATS (WS_FLOATS + HD_FLOATS + GB_FLOATS)
#define SMEM2_BYTES (SMEM2_FLOATS * 4)        // 219,264 B <= 227 KB

__device__ __forceinline__ int hd_off(int b) { return 2 * b + 2 * (b >> 4); }

__global__ __launch_bounds__(256, 1) void lstm_persist(
    const float* __restrict__ Whh,  // [4H][H]
    float* __restrict__ out)
{
    extern __shared__ float sm[];
    float* Ws   = sm;                       // [1024][36]
    float* Hd   = sm + WS_FLOATS;           // [buf][kk][64][66]
    float* gbuf = Hd + HD_FLOATS;           // [32][33]

    int tid = threadIdx.x;
    int bid = blockIdx.x;

    // ---- stage W_hh slice into smem once (transposed: Ws[k*36 + row]) ----
    {
        int r  = tid >> 3;          // 0..31 gate-row index (g*8+u)
        int kq = tid & 7;
        int grow = (r >> 3) * Hn + bid * 8 + (r & 7);
        const float* wr = Whh + (size_t)grow * Hn;
#pragma unroll 4
        for (int m = 0; m < 32; m++) {
            int k = m * 32 + kq * 4;
            float4 v = *(const float4*)(wr + k);
            Ws[(k + 0) * WS_STRIDE + r] = v.x;
            Ws[(k + 1) * WS_STRIDE + r] = v.y;
            Ws[(k + 2) * WS_STRIDE + r] = v.z;
            Ws[(k + 3) * WS_STRIDE + r] = v.w;
        }
    }

    int kk = tid >> 7;          // k-half
    int t2 = tid & 127;
    int rg = t2 >> 4;           // 4 rows: 4rg..4rg+3
    int bg = t2 & 15;           // batches 2bg, 2bg+1
    int off0 = hd_off(2 * bg);
    int off1 = hd_off(2 * bg + 1);
    int sb = tid & 31;
    int sq = tid >> 5;          // 0..7
    int eb = tid >> 3;          // batch 0..31
    int ej = tid & 7;           // unit 0..7
    int hidx = bid * 8 + ej;
    int ci = eb * Hn + hidx;

    __syncthreads();

    for (int t = 0; t < Tn; t++) {
        const float* hin = g_h + (t & 1) * (Bn * Hn);
        float* hout      = g_h + ((t + 1) & 1) * (Bn * Hn);

        const float* xp = g_xpre + ((size_t)t * Bn + eb) * Gn;
        float xpi = __ldg(xp + hidx);
        float xpf = __ldg(xp + Hn + hidx);
        float xpg = __ldg(xp + 2 * Hn + hidx);
        float xpo = __ldg(xp + 3 * Hn + hidx);

        // ---- stage tile 0 (both kk windows), duplicated pairs ----
#pragma unroll
        for (int kkh = 0; kkh < 2; kkh++) {
            float4 v0 = __ldcg((const float4*)(hin + sb * Hn + kkh * 512 + sq * 8));
            float4 v1 = __ldcg((const float4*)(hin + sb * Hn + kkh * 512 + sq * 8 + 4));
            float* dst = Hd + kkh * HD_HALF + (sq * 8) * HD_ROW + hd_off(sb);
            const float* pv = (const float*)&v0;
#pragma unroll
            for (int i = 0; i < 4; i++) *(float2*)(dst + i * HD_ROW) = make_float2(pv[i], pv[i]);
            pv = (const float*)&v1;
#pragma unroll
            for (int i = 0; i < 4; i++) *(float2*)(dst + (4 + i) * HD_ROW) = make_float2(pv[i], pv[i]);
        }
        __syncthreads();

        ull a00 = 0ULL, a01 = 0ULL, a10 = 0ULL, a11 = 0ULL;

        for (int tile = 0; tile < 8; tile++) {
            float4 p0a, p0b, p1a, p1b;
            if (tile < 7) {
                int kb0 = (tile + 1) * 64 + sq * 8;
                p0a = __ldcg((const float4*)(hin + sb * Hn + kb0));
                p0b = __ldcg((const float4*)(hin + sb * Hn + kb0 + 4));
                p1a = __ldcg((const float4*)(hin + sb * Hn + 512 + kb0));
                p1b = __ldcg((const float4*)(hin + sb * Hn + 512 + kb0 + 4));
            }
            int buf = tile & 1;
            const float* wk = Ws + (size_t)(kk * 512 + tile * 64) * WS_STRIDE + 4 * rg;
            const float* hb = Hd + buf * (2 * HD_HALF) + kk * HD_HALF;
#pragma unroll 16
            for (int kl = 0; kl < 64; kl++) {
                ulonglong2 w = *(const ulonglong2*)(wk + kl * WS_STRIDE);
                ull h0 = *(const ull*)(hb + kl * HD_ROW + off0);
                ull h1 = *(const ull*)(hb + kl * HD_ROW + off1);
                a00 = fma2(w.x, h0, a00);
                a01 = fma2(w.x, h1, a01);
                a10 = fma2(w.y, h0, a10);
                a11 = fma2(w.y, h1, a11);
            }
            if (tile < 7) {
                int nbuf = buf ^ 1;
                float* d0 = Hd + nbuf * (2 * HD_HALF) + (sq * 8) * HD_ROW + hd_off(sb);
                float* d1 = d0 + HD_HALF;
                const float* pv = (const float*)&p0a;
#pragma unroll
                for (int i = 0; i < 4; i++) *(float2*)(d0 + i * HD_ROW) = make_float2(pv[i], pv[i]);
                pv = (const float*)&p0b;
#pragma unroll
                for (int i = 0; i < 4; i++) *(float2*)(d0 + (4 + i) * HD_ROW) = make_float2(pv[i], pv[i]);
                pv = (const float*)&p1a;
#pragma unroll
                for (int i = 0; i < 4; i++) *(float2*)(d1 + i * HD_ROW) = make_float2(pv[i], pv[i]);
                pv = (const float*)&p1b;
#pragma unroll
                for (int i = 0; i < 4; i++) *(float2*)(d1 + (4 + i) * HD_ROW) = make_float2(pv[i], pv[i]);
            }
            __syncthreads();
        }

        // ---- reduce the two k-halves into gbuf ----
        {
            float l, h;
            if (kk == 0) {
                unpack2(a00, l, h); gbuf[(4*rg+0)*33 + 2*bg]   = l; gbuf[(4*rg+1)*33 + 2*bg]   = h;
                unpack2(a01, l, h); gbuf[(4*rg+0)*33 + 2*bg+1] = l; gbuf[(4*rg+1)*33 + 2*bg+1] = h;
                unpack2(a10, l, h); gbuf[(4*rg+2)*33 + 2*bg]   = l; gbuf[(4*rg+3)*33 + 2*bg]   = h;
                unpack2(a11, l, h); gbuf[(4*rg+2)*33 + 2*bg+1] = l; gbuf[(4*rg+3)*33 + 2*bg+1] = h;
            }
            __syncthreads();
            if (kk == 1) {
                unpack2(a00, l, h); gbuf[(4*rg+0)*33 + 2*bg]   += l; gbuf[(4*rg+1)*33 + 2*bg]   += h;
                unpack2(a01, l, h); gbuf[(4*rg+0)*33 + 2*bg+1] += l; gbuf[(4*rg+1)*33 + 2*bg+1] += h;
                unpack2(a10, l, h); gbuf[(4*rg+2)*33 + 2*bg]   += l; gbuf[(4*rg+3)*33 + 2*bg]   += h;
                unpack2(a11, l, h); gbuf[(4*rg+2)*33 + 2*bg+1] += l; gbuf[(4*rg+3)*33 + 2*bg+1] += h;
            }
            __syncthreads();
        }

        // ---- LSTM elementwise ----
        {
            float pi = gbuf[(0  + ej) * 33 + eb] + xpi;
            float pf = gbuf[(8  + ej) * 33 + eb] + xpf;
            float pg = gbuf[(16 + ej) * 33 + eb] + xpg;
            float po = gbuf[(24 + ej) * 33 + eb] + xpo;
            float ig = 1.0f / (1.0f + __expf(-pi));
            float fg = 1.0f / (1.0f + __expf(-pf));
            float gg = tanhf(pg);
            float og = 1.0f / (1.0f + __expf(-po));
            float c = fg * g_c[ci] + ig * gg;
            float h = og * tanhf(c);
            g_c[ci]  = c;
            hout[ci] = h;
            out[((size_t)eb * Tn + t) * Hn + hidx] = h;
            if (t == Tn - 1) {
                out[(size_t)Bn * Tn * Hn + ci]           = h;  // h_T
                out[(size_t)Bn * Tn * Hn + Bn * Hn + ci] = c;  // c_T
            }
        }

        // ---- grid barrier (software; all 128 blocks co-resident) ----
        if (t < Tn - 1) {
            __threadfence();
            __syncthreads();
            if (tid == 0) {
                unsigned target = (unsigned)NB * (unsigned)(t + 1);
                if (atomicAdd(&g_count, 1u) == target - 1u) {
                    __threadfence();
                    g_gen = (unsigned)(t + 1);
                } else {
                    while (g_gen < (unsigned)(t + 1)) { }
                    __threadfence();
                }
            }
            __syncthreads();
        }
    }
}

// ---------------- launch ----------------
extern "C" void kernel_launch(void* const* d_in, const int* in_sizes, int n_in,
                              void* d_out, int out_size)
{
    const float* X   = (const float*)d_in[0];
    const float* Wih = (const float*)d_in[1];
    const float* Whh = (const float*)d_in[2];
    const float* bih = (const float*)d_in[3];
    const float* bhh = (const float*)d_in[4];
    float* out = (float*)d_out;

    cudaFuncSetAttribute(lstm_persist, cudaFuncAttributeMaxDynamicSharedMemorySize, SMEM2_BYTES);

    prep_gemm<<<dim3(Gn / 128, (Tn * Bn) / 128), 256>>>(X, Wih, bih, bhh);
    lstm_persist<<<NB, 256, SMEM2_BYTES>>>(Whh, out);
}

// round 9
// speedup vs baseline: 1.1639x; 1.1639x over previous
#include <cuda_runtime.h>
#include <cstdint>

#define Bn 32
#define Tn 1024
#define In 512
#define Hn 1024
#define Gn 4096   // 4*Hn
#define NB 128    // persistent blocks (1 block/SM)
#define NT 512    // phase-2 threads

// ---------------- device scratch (static: no allocation allowed) ----------------
__device__ float g_xpre[(size_t)Tn * Bn * Gn];  // [T][B][4H], biases folded in
__device__ float g_h[2 * Bn * Hn];              // ping-pong hidden state
__device__ float g_c[Bn * Hn];                  // cell state (block-exclusive ranges)
__device__ unsigned g_count;                    // grid barrier arrivals (monotonic)
__device__ volatile unsigned g_gen;             // grid barrier generation

typedef unsigned long long ull;

__device__ __forceinline__ ull fma2(ull a, ull b, ull c) {
    ull d; asm("fma.rn.f32x2 %0, %1, %2, %3;" : "=l"(d) : "l"(a), "l"(b), "l"(c)); return d;
}
__device__ __forceinline__ ull pack2(float lo, float hi) {
    ull r; asm("mov.b64 %0, {%1, %2};" : "=l"(r) : "f"(lo), "f"(hi)); return r;
}
__device__ __forceinline__ void unpack2(ull v, float& a, float& b) {
    asm("mov.b64 {%0, %1}, %2;" : "=f"(a), "=f"(b) : "l"(v));
}

// ---------------- phase 1 (+init): Xpre = inputs @ W_ih^T + b_ih + b_hh ----------------
// (validated) M = T*B = 32768, N = 4096, K = 512. 128x128 tiles, f32x2.
__global__ __launch_bounds__(256) void prep_gemm(
    const float* __restrict__ X,    // [B][T][I]
    const float* __restrict__ Wih,  // [4H][I]
    const float* __restrict__ bih,
    const float* __restrict__ bhh)
{
    __shared__ float As[2][16][132];
    __shared__ float Bs[2][16][132];

    int tid = threadIdx.x;
    int bx = blockIdx.x, by = blockIdx.y;

    // ---- fused init of state/barrier ----
    {
        int fb = by * 32 + bx;
        int idx = fb * 256 + tid;
        if (idx < 2 * Bn * Hn) g_h[idx] = 0.0f;
        if (idx < Bn * Hn)     g_c[idx] = 0.0f;
        if (idx == 0) { g_count = 0; g_gen = 0; }
    }

    int sr = tid & 127;
    int sk = (tid >> 7) * 8;
    int mg = by * 128 + sr;
    const float* arow = X + ((size_t)(mg & 31) * Tn + (mg >> 5)) * In;
    const float* brow = Wih + (size_t)(bx * 128 + sr) * In;

    int tm = tid >> 4;
    int tn = tid & 15;

    ull acc[8][4];
#pragma unroll
    for (int i = 0; i < 8; i++)
#pragma unroll
        for (int p = 0; p < 4; p++) acc[i][p] = 0ULL;

    float4 pa0, pa1, pb0, pb1;
    pa0 = *(const float4*)(arow + sk);
    pa1 = *(const float4*)(arow + sk + 4);
    pb0 = *(const float4*)(brow + sk);
    pb1 = *(const float4*)(brow + sk + 4);
#pragma unroll
    for (int j = 0; j < 4; j++) {
        As[0][sk + j][sr]     = ((const float*)&pa0)[j];
        As[0][sk + 4 + j][sr] = ((const float*)&pa1)[j];
        Bs[0][sk + j][sr]     = ((const float*)&pb0)[j];
        Bs[0][sk + 4 + j][sr] = ((const float*)&pb1)[j];
    }
    __syncthreads();

    for (int kt = 0; kt < 32; kt++) {
        if (kt < 31) {
            int k0 = (kt + 1) * 16;
            pa0 = *(const float4*)(arow + k0 + sk);
            pa1 = *(const float4*)(arow + k0 + sk + 4);
            pb0 = *(const float4*)(brow + k0 + sk);
            pb1 = *(const float4*)(brow + k0 + sk + 4);
        }
        int buf = kt & 1;
#pragma unroll
        for (int k = 0; k < 16; k++) {
            float a[8];
            *(float4*)&a[0] = *(const float4*)&As[buf][k][tm * 8];
            *(float4*)&a[4] = *(const float4*)&As[buf][k][tm * 8 + 4];
            float4 b0 = *(const float4*)&Bs[buf][k][tn * 8];
            float4 b1 = *(const float4*)&Bs[buf][k][tn * 8 + 4];
            ull bv[4];
            bv[0] = *(const ull*)&b0.x; bv[1] = *(const ull*)&b0.z;
            bv[2] = *(const ull*)&b1.x; bv[3] = *(const ull*)&b1.z;
#pragma unroll
            for (int i = 0; i < 8; i++) {
                ull ap = pack2(a[i], a[i]);
#pragma unroll
                for (int p = 0; p < 4; p++)
                    acc[i][p] = fma2(ap, bv[p], acc[i][p]);
            }
        }
        if (kt < 31) {
            int nb = (kt + 1) & 1;
#pragma unroll
            for (int j = 0; j < 4; j++) {
                As[nb][sk + j][sr]     = ((const float*)&pa0)[j];
                As[nb][sk + 4 + j][sr] = ((const float*)&pa1)[j];
                Bs[nb][sk + j][sr]     = ((const float*)&pb0)[j];
                Bs[nb][sk + 4 + j][sr] = ((const float*)&pb1)[j];
            }
        }
        __syncthreads();
    }

    int ng = bx * 128 + tn * 8;
    float bias[8];
#pragma unroll
    for (int j = 0; j < 8; j++) bias[j] = bih[ng + j] + bhh[ng + j];
#pragma unroll
    for (int i = 0; i < 8; i++) {
        int m = by * 128 + tm * 8 + i;
        float* dst = g_xpre + (size_t)m * Gn + ng;
#pragma unroll
        for (int p = 0; p < 4; p++) {
            float lo, hi; unpack2(acc[i][p], lo, hi);
            *(float2*)(dst + 2 * p) = make_float2(lo + bias[2 * p], hi + bias[2 * p + 1]);
        }
    }
}

// ---------------- phase 2: persistent LSTM, 512 threads ----------------
// Block owns 32 gate rows (4 gates x 8 units) x 32 batches, K=1024.
// W_hh slice resident in smem (transposed Ws[k][row], stride 36).
// k split 8 ways (kq = tid>>6); shared 64-k double-buffered h window per tile.
// Thread micro-tile: 4 rows (4rg..4rg+3) x 4 batches (4bgr..4bgr+3), 8 fma2/kl.
// Duplicated-h layout bank-swizzled: batch-group g at float offset 8g + 4(g>>2).
#define WS_STRIDE 36
#define WS_FLOATS (Hn * WS_STRIDE)            // 36864
#define HD_ROW 68
#define HD_BUF (64 * HD_ROW)                  // 4352
#define HD_FLOATS (2 * HD_BUF)                // 8704 (>= P_FLOATS 8448, overlaid)
#define GB_FLOATS (32 * 33)                   // 1056
#define SMEM2_FLOATS (WS_FLOATS + HD_FLOATS + GB_FLOATS)
#define SMEM2_BYTES (SMEM2_FLOATS * 4)        // 186,496 B

__global__ __launch_bounds__(NT, 1) void lstm_persist(
    const float* __restrict__ Whh,  // [4H][H]
    float* __restrict__ out)
{
    extern __shared__ float sm[];
    float* Ws   = sm;                       // [1024][36]
    float* Hd   = sm + WS_FLOATS;           // [2][64][68] (dup h) / overlay P[8][32][33]
    float* gbuf = sm + WS_FLOATS + HD_FLOATS;  // [32][33]
    float* P    = Hd;

    int tid = threadIdx.x;
    int bid = blockIdx.x;

    // ---- stage W_hh slice (once): Ws[k*36 + row], row = gate*8 + unit ----
    {
        int r   = tid >> 4;            // 0..31
        int kq4 = (tid & 15) * 4;
        int grow = (r >> 3) * Hn + bid * 8 + (r & 7);
        const float* wr = Whh + (size_t)grow * Hn;
#pragma unroll 4
        for (int m = 0; m < 16; m++) {
            int k = m * 64 + kq4;
            float4 v = *(const float4*)(wr + k);
            Ws[(k + 0) * WS_STRIDE + r] = v.x;
            Ws[(k + 1) * WS_STRIDE + r] = v.y;
            Ws[(k + 2) * WS_STRIDE + r] = v.z;
            Ws[(k + 3) * WS_STRIDE + r] = v.w;
        }
    }

    // compute mapping
    int kq  = tid >> 6;          // 0..7 k-group (8 k per tile)
    int t6  = tid & 63;
    int rg  = t6 >> 3;           // 0..7 -> rows 4rg..4rg+3
    int bgr = t6 & 7;            // 0..7 -> batches 4bgr..4bgr+3
    int hoff = 8 * bgr + 4 * (bgr >> 2);   // swizzled dup-offset of batch group
    // staging mapping: batch sb, 4 k values at sk4
    int sb  = tid & 31;
    int sk4 = (tid >> 5) * 4;    // 0..60
    int sboff = 8 * (sb >> 2) + 4 * (sb >> 4) + 2 * (sb & 3);  // dup offset of batch sb
    // elementwise mapping (tid < 256)
    int eb = tid >> 3;           // batch 0..31
    int ej = tid & 7;            // unit 0..7
    int hidx = bid * 8 + ej;
    int ci = eb * Hn + hidx;

    __syncthreads();

    for (int t = 0; t < Tn; t++) {
        const float* hin = g_h + (t & 1) * (Bn * Hn);
        float* hout      = g_h + ((t + 1) & 1) * (Bn * Hn);

        float xpi, xpf, xpg, xpo;
        if (tid < 256) {
            const float* xp = g_xpre + ((size_t)t * Bn + eb) * Gn;
            xpi = __ldg(xp + hidx);
            xpf = __ldg(xp + Hn + hidx);
            xpg = __ldg(xp + 2 * Hn + hidx);
            xpo = __ldg(xp + 3 * Hn + hidx);
        }

        // ---- stage tile 0 into buf 0 ----
        {
            float4 v = __ldcg((const float4*)(hin + sb * Hn + sk4));
            float* dst = Hd + sk4 * HD_ROW + sboff;
            dst[0]            = v.x; dst[1]            = v.x;
            dst[HD_ROW]       = v.y; dst[HD_ROW + 1]   = v.y;
            dst[2 * HD_ROW]   = v.z; dst[2 * HD_ROW+1] = v.z;
            dst[3 * HD_ROW]   = v.w; dst[3 * HD_ROW+1] = v.w;
        }
        __syncthreads();

        ull acc[2][4];
#pragma unroll
        for (int p = 0; p < 2; p++)
#pragma unroll
            for (int b = 0; b < 4; b++) acc[p][b] = 0ULL;

#pragma unroll 2
        for (int tile = 0; tile < 16; tile++) {
            float4 pf;
            if (tile < 15)
                pf = __ldcg((const float4*)(hin + sb * Hn + (tile + 1) * 64 + sk4));
            int buf = tile & 1;
            const float* wk = Ws + (size_t)(tile * 64 + kq * 8) * WS_STRIDE + 4 * rg;
            const float* hb = Hd + buf * HD_BUF + (kq * 8) * HD_ROW + hoff;
#pragma unroll
            for (int kl = 0; kl < 8; kl++) {
                ulonglong2 w  = *(const ulonglong2*)(wk + kl * WS_STRIDE);
                ulonglong2 h0 = *(const ulonglong2*)(hb + kl * HD_ROW);
                ulonglong2 h1 = *(const ulonglong2*)(hb + kl * HD_ROW + 4);
                acc[0][0] = fma2(w.x, h0.x, acc[0][0]);
                acc[1][0] = fma2(w.y, h0.x, acc[1][0]);
                acc[0][1] = fma2(w.x, h0.y, acc[0][1]);
                acc[1][1] = fma2(w.y, h0.y, acc[1][1]);
                acc[0][2] = fma2(w.x, h1.x, acc[0][2]);
                acc[1][2] = fma2(w.y, h1.x, acc[1][2]);
                acc[0][3] = fma2(w.x, h1.y, acc[0][3]);
                acc[1][3] = fma2(w.y, h1.y, acc[1][3]);
            }
            if (tile < 15) {
                float* dst = Hd + (buf ^ 1) * HD_BUF + sk4 * HD_ROW + sboff;
                dst[0]            = pf.x; dst[1]            = pf.x;
                dst[HD_ROW]       = pf.y; dst[HD_ROW + 1]   = pf.y;
                dst[2 * HD_ROW]   = pf.z; dst[2 * HD_ROW+1] = pf.z;
                dst[3 * HD_ROW]   = pf.w; dst[3 * HD_ROW+1] = pf.w;
            }
            __syncthreads();
        }

        // ---- write per-k-group partials into P (overlay of Hd; reads done) ----
#pragma unroll
        for (int p = 0; p < 2; p++)
#pragma unroll
            for (int b = 0; b < 4; b++) {
                float lo, hi; unpack2(acc[p][b], lo, hi);
                int col = 4 * bgr + b;
                P[kq * 1056 + (4 * rg + 2 * p)     * 33 + col] = lo;
                P[kq * 1056 + (4 * rg + 2 * p + 1) * 33 + col] = hi;
            }
        __syncthreads();

        // ---- reduce 8 k-groups: 1024 outputs, 2 per thread ----
#pragma unroll
        for (int rep = 0; rep < 2; rep++) {
            int gid = tid + rep * NT;
            int row = gid >> 5, b = gid & 31;
            float s = 0.0f;
#pragma unroll
            for (int q = 0; q < 8; q++) s += P[q * 1056 + row * 33 + b];
            gbuf[row * 33 + b] = s;
        }
        __syncthreads();

        // ---- LSTM elementwise (256 cells) ----
        if (tid < 256) {
            float pi = gbuf[(0  + ej) * 33 + eb] + xpi;
            float pf_ = gbuf[(8  + ej) * 33 + eb] + xpf;
            float pg = gbuf[(16 + ej) * 33 + eb] + xpg;
            float po = gbuf[(24 + ej) * 33 + eb] + xpo;
            float ig = 1.0f / (1.0f + __expf(-pi));
            float fg = 1.0f / (1.0f + __expf(-pf_));
            float gg = tanhf(pg);
            float og = 1.0f / (1.0f + __expf(-po));
            float c = fg * g_c[ci] + ig * gg;
            float h = og * tanhf(c);
            g_c[ci]  = c;
            hout[ci] = h;
            out[((size_t)eb * Tn + t) * Hn + hidx] = h;
            if (t == Tn - 1) {
                out[(size_t)Bn * Tn * Hn + ci]           = h;  // h_T
                out[(size_t)Bn * Tn * Hn + Bn * Hn + ci] = c;  // c_T
            }
        }

        // ---- grid barrier (validated pattern) ----
        if (t < Tn - 1) {
            __threadfence();
            __syncthreads();
            if (tid == 0) {
                unsigned target = (unsigned)NB * (unsigned)(t + 1);
                if (atomicAdd(&g_count, 1u) == target - 1u) {
                    __threadfence();
                    g_gen = (unsigned)(t + 1);
                } else {
                    while (g_gen < (unsigned)(t + 1)) { }
                    __threadfence();
                }
            }
            __syncthreads();
        }
    }
}

// ---------------- launch ----------------
extern "C" void kernel_launch(void* const* d_in, const int* in_sizes, int n_in,
                              void* d_out, int out_size)
{
    const float* X   = (const float*)d_in[0];
    const float* Wih = (const float*)d_in[1];
    const float* Whh = (const float*)d_in[2];
    const float* bih = (const float*)d_in[3];
    const float* bhh = (const float*)d_in[4];
    float* out = (float*)d_out;

    cudaFuncSetAttribute(lstm_persist, cudaFuncAttributeMaxDynamicSharedMemorySize, SMEM2_BYTES);

    prep_gemm<<<dim3(Gn / 128, (Tn * Bn) / 128), 256>>>(X, Wih, bih, bhh);
    lstm_persist<<<NB, NT, SMEM2_BYTES>>>(Whh, out);
}